// round 2
// baseline (speedup 1.0000x reference)
#include <cuda_runtime.h>

// Problem constants
#define BB 16
#define LL 4096
#define DD 512
#define KK 2048           // codebook size
#define GG (LL / 2)       // groups per sequence
#define NROWS (BB * GG)   // 32768 word positions

// Scratch (device globals; no allocation allowed)
__device__ float g_means[NROWS * DD];   // 64 MiB
__device__ int   g_idx[NROWS];
__device__ float g_cbsq[KK];
__device__ float g_s[KK];

// ---------------------------------------------------------------------------
// K1: means[n,d] = 0.5*(E[2n,d] + E[2n+1,d]), vectorized float4
// ---------------------------------------------------------------------------
__global__ void means_kernel(const float4* __restrict__ E) {
    int i = blockIdx.x * blockDim.x + threadIdx.x;  // over NROWS * DD/4
    const int D4 = DD / 4;
    if (i >= NROWS * D4) return;
    int row = i / D4;
    int d4  = i - row * D4;
    float4 a = E[(2 * row) * D4 + d4];
    float4 b = E[(2 * row + 1) * D4 + d4];
    float4 m;
    m.x = 0.5f * (a.x + b.x);
    m.y = 0.5f * (a.y + b.y);
    m.z = 0.5f * (a.z + b.z);
    m.w = 0.5f * (a.w + b.w);
    ((float4*)g_means)[i] = m;
}

// ---------------------------------------------------------------------------
// K2: per-code prep.  Block handles 8 codebook rows.
//   g_cbsq[k] = ||C[k]||^2
//   g_s[k]    = sum_e (C[k]·W[e,:] + b[e] - C[k][e])^2
// ---------------------------------------------------------------------------
__global__ __launch_bounds__(256) void prep_kernel(const float* __restrict__ Cb,
                                                   const float* __restrict__ W,
                                                   const float* __restrict__ bias) {
    __shared__ float Ck[8][DD];
    __shared__ float sred[8][8];  // [warp][k]
    int tid  = threadIdx.x;
    int warp = tid >> 5;
    int lane = tid & 31;
    int k0   = blockIdx.x * 8;

    for (int i = tid; i < 8 * DD; i += 256) {
        int kk = i / DD, d = i - kk * DD;
        Ck[kk][d] = Cb[(k0 + kk) * DD + d];
    }
    __syncthreads();

    // cbsq: warp w handles local row w
    {
        float sq = 0.f;
        for (int d = lane; d < DD; d += 32) {
            float v = Ck[warp][d];
            sq = fmaf(v, v, sq);
        }
        #pragma unroll
        for (int o = 16; o; o >>= 1) sq += __shfl_xor_sync(0xffffffffu, sq, o);
        if (lane == 0) g_cbsq[k0 + warp] = sq;
    }

    float sacc[8];
    #pragma unroll
    for (int kk = 0; kk < 8; kk++) sacc[kk] = 0.f;

    for (int e = warp; e < DD; e += 8) {
        float p[8];
        #pragma unroll
        for (int kk = 0; kk < 8; kk++) p[kk] = 0.f;
        for (int d = lane; d < DD; d += 32) {
            float wv = W[e * DD + d];  // coalesced
            #pragma unroll
            for (int kk = 0; kk < 8; kk++) p[kk] = fmaf(Ck[kk][d], wv, p[kk]);
        }
        #pragma unroll
        for (int kk = 0; kk < 8; kk++) {
            #pragma unroll
            for (int o = 16; o; o >>= 1) p[kk] += __shfl_xor_sync(0xffffffffu, p[kk], o);
        }
        if (lane == 0) {
            float be = bias[e];
            #pragma unroll
            for (int kk = 0; kk < 8; kk++) {
                float diff = p[kk] + be - Ck[kk][e];
                sacc[kk] = fmaf(diff, diff, sacc[kk]);
            }
        }
    }
    if (lane == 0) {
        #pragma unroll
        for (int kk = 0; kk < 8; kk++) sred[warp][kk] = sacc[kk];
    }
    __syncthreads();
    if (tid < 8) {
        float s = 0.f;
        #pragma unroll
        for (int w = 0; w < 8; w++) s += sred[w][tid];
        g_s[k0 + tid] = s;
    }
}

// ---------------------------------------------------------------------------
// K3: fused SGEMM + argmin.
//   Block: 128 rows x all 2048 codes (looped in tiles of 128), 256 threads,
//   8x8 microtile per thread, fp32 FFMA, running (min, argmin) in registers.
//   score[n,k] = cbsq[k] - 2 * dot(means[n], C[k])
// ---------------------------------------------------------------------------
#define RT 128
#define CT 128
#define KT 8

__global__ __launch_bounds__(256, 2) void argmin_gemm(const float* __restrict__ Cb,
                                                      float* __restrict__ out_idx_f) {
    __shared__ float As[KT][RT];
    __shared__ float Bs[KT][CT];
    __shared__ float sq_s[CT];
    __shared__ float redv[RT][17];
    __shared__ int   redi[RT][17];

    int tid = threadIdx.x;
    int tx  = tid & 15;   // code dim
    int ty  = tid >> 4;   // row dim
    int row0 = blockIdx.x * RT;

    float minv[8];
    int   mini[8];
    #pragma unroll
    for (int r = 0; r < 8; r++) { minv[r] = 3.4e38f; mini[r] = 0; }

    const int ldr  = tid >> 1;          // 0..127
    const int koff = (tid & 1) * 4;     // 0 or 4

    for (int ct = 0; ct < KK; ct += CT) {
        if (tid < CT) sq_s[tid] = g_cbsq[ct + tid];

        float acc[8][8];
        #pragma unroll
        for (int r = 0; r < 8; r++)
            #pragma unroll
            for (int c = 0; c < 8; c++) acc[r][c] = 0.f;

        for (int d0 = 0; d0 < DD; d0 += KT) {
            // stage tiles (transposed into smem)
            float4 va = *(const float4*)&g_means[(row0 + ldr) * DD + d0 + koff];
            float4 vb = *(const float4*)&Cb[(ct + ldr) * DD + d0 + koff];
            As[koff + 0][ldr] = va.x; As[koff + 1][ldr] = va.y;
            As[koff + 2][ldr] = va.z; As[koff + 3][ldr] = va.w;
            Bs[koff + 0][ldr] = vb.x; Bs[koff + 1][ldr] = vb.y;
            Bs[koff + 2][ldr] = vb.z; Bs[koff + 3][ldr] = vb.w;
            __syncthreads();

            #pragma unroll
            for (int kkk = 0; kkk < KT; kkk++) {
                float a[8], b[8];
                *(float4*)(a)     = *(const float4*)&As[kkk][ty * 8];
                *(float4*)(a + 4) = *(const float4*)&As[kkk][ty * 8 + 4];
                *(float4*)(b)     = *(const float4*)&Bs[kkk][tx * 8];
                *(float4*)(b + 4) = *(const float4*)&Bs[kkk][tx * 8 + 4];
                #pragma unroll
                for (int r = 0; r < 8; r++)
                    #pragma unroll
                    for (int c = 0; c < 8; c++)
                        acc[r][c] = fmaf(a[r], b[c], acc[r][c]);
            }
            __syncthreads();
        }

        // fold tile into running argmin
        #pragma unroll
        for (int c = 0; c < 8; c++) {
            float q = sq_s[tx * 8 + c];
            int code = ct + tx * 8 + c;
            #pragma unroll
            for (int r = 0; r < 8; r++) {
                float s = fmaf(-2.0f, acc[r][c], q);
                if (s < minv[r]) { minv[r] = s; mini[r] = code; }
            }
        }
        __syncthreads();  // protect sq_s before next tile's rewrite
    }

    // cross-thread reduce: 16 tx candidates per row
    #pragma unroll
    for (int r = 0; r < 8; r++) {
        redv[ty * 8 + r][tx] = minv[r];
        redi[ty * 8 + r][tx] = mini[r];
    }
    __syncthreads();
    if (tid < RT) {
        float bv = redv[tid][0];
        int   bi = redi[tid][0];
        #pragma unroll
        for (int j = 1; j < 16; j++) {
            float v = redv[tid][j];
            int   i2 = redi[tid][j];
            if (v < bv || (v == bv && i2 < bi)) { bv = v; bi = i2; }
        }
        g_idx[row0 + tid] = bi;
        out_idx_f[row0 + tid] = (float)bi;
    }
}

// ---------------------------------------------------------------------------
// K4: gather word embeddings
// ---------------------------------------------------------------------------
__global__ void gather_kernel(const float4* __restrict__ Cb4, float4* __restrict__ out4) {
    int n = blockIdx.x;
    int idx = g_idx[n];
    out4[n * (DD / 4) + threadIdx.x] = Cb4[idx * (DD / 4) + threadIdx.x];
}

// ---------------------------------------------------------------------------
// K5: deterministic loss reduction: mean over B*G*D of per-row s[idx]
// ---------------------------------------------------------------------------
__global__ void loss_kernel(float* __restrict__ out_loss) {
    __shared__ float red[1024];
    float s = 0.f;
    for (int n = threadIdx.x; n < NROWS; n += 1024) s += g_s[g_idx[n]];
    red[threadIdx.x] = s;
    __syncthreads();
    for (int st = 512; st > 0; st >>= 1) {
        if (threadIdx.x < st) red[threadIdx.x] += red[threadIdx.x + st];
        __syncthreads();
    }
    if (threadIdx.x == 0)
        out_loss[0] = red[0] / (float)((long long)NROWS * DD);
}

// ---------------------------------------------------------------------------
extern "C" void kernel_launch(void* const* d_in, const int* in_sizes, int n_in,
                              void* d_out, int out_size) {
    // inputs: [0] char_tokens (unused), [1] char_embeddings, [2] word_codebook,
    //         [3] proj_w, [4] proj_b
    const float* E    = (const float*)d_in[1];
    const float* Cb   = (const float*)d_in[2];
    const float* W    = (const float*)d_in[3];
    const float* bias = (const float*)d_in[4];

    float* out      = (float*)d_out;
    float* out_idx  = out;                       // NROWS
    float* out_emb  = out + NROWS;               // NROWS*DD
    float* out_loss = out + NROWS + NROWS * DD;  // 1

    means_kernel<<<(NROWS * (DD / 4) + 255) / 256, 256>>>((const float4*)E);
    prep_kernel<<<KK / 8, 256>>>(Cb, W, bias);
    argmin_gemm<<<NROWS / RT, 256>>>(Cb, out_idx);
    gather_kernel<<<NROWS, DD / 4>>>((const float4*)Cb, (float4*)out_emb);
    loss_kernel<<<1, 1024>>>(out_loss);
}

// round 3
// speedup vs baseline: 1.0001x; 1.0001x over previous
#include <cuda_runtime.h>

// Problem constants
#define BB 16
#define LL 4096
#define DD 512
#define KK 2048           // codebook size
#define GG (LL / 2)       // groups per sequence
#define NROWS (BB * GG)   // 32768 word positions

// Scratch (device globals; no allocation allowed)
__device__ float g_means[NROWS * DD];   // 64 MiB
__device__ int   g_idx[NROWS];
__device__ float g_cbsq[KK];
__device__ float g_s[KK];

// ---------------------------------------------------------------------------
// K1: means[n,d] = 0.5*(E[2n,d] + E[2n+1,d]), vectorized float4
// ---------------------------------------------------------------------------
__global__ void means_kernel(const float4* __restrict__ E) {
    int i = blockIdx.x * blockDim.x + threadIdx.x;  // over NROWS * DD/4
    const int D4 = DD / 4;
    if (i >= NROWS * D4) return;
    int row = i / D4;
    int d4  = i - row * D4;
    float4 a = E[(2 * row) * D4 + d4];
    float4 b = E[(2 * row + 1) * D4 + d4];
    float4 m;
    m.x = 0.5f * (a.x + b.x);
    m.y = 0.5f * (a.y + b.y);
    m.z = 0.5f * (a.z + b.z);
    m.w = 0.5f * (a.w + b.w);
    ((float4*)g_means)[i] = m;
}

// ---------------------------------------------------------------------------
// K2: per-code prep.  Block handles 8 codebook rows.
//   g_cbsq[k] = ||C[k]||^2
//   g_s[k]    = sum_e (C[k]·W[e,:] + b[e] - C[k][e])^2
// ---------------------------------------------------------------------------
__global__ __launch_bounds__(256) void prep_kernel(const float* __restrict__ Cb,
                                                   const float* __restrict__ W,
                                                   const float* __restrict__ bias) {
    __shared__ float Ck[8][DD];
    __shared__ float sred[8][8];  // [warp][k]
    int tid  = threadIdx.x;
    int warp = tid >> 5;
    int lane = tid & 31;
    int k0   = blockIdx.x * 8;

    for (int i = tid; i < 8 * DD; i += 256) {
        int kk = i / DD, d = i - kk * DD;
        Ck[kk][d] = Cb[(k0 + kk) * DD + d];
    }
    __syncthreads();

    // cbsq: warp w handles local row w
    {
        float sq = 0.f;
        for (int d = lane; d < DD; d += 32) {
            float v = Ck[warp][d];
            sq = fmaf(v, v, sq);
        }
        #pragma unroll
        for (int o = 16; o; o >>= 1) sq += __shfl_xor_sync(0xffffffffu, sq, o);
        if (lane == 0) g_cbsq[k0 + warp] = sq;
    }

    float sacc[8];
    #pragma unroll
    for (int kk = 0; kk < 8; kk++) sacc[kk] = 0.f;

    for (int e = warp; e < DD; e += 8) {
        float p[8];
        #pragma unroll
        for (int kk = 0; kk < 8; kk++) p[kk] = 0.f;
        for (int d = lane; d < DD; d += 32) {
            float wv = W[e * DD + d];  // coalesced
            #pragma unroll
            for (int kk = 0; kk < 8; kk++) p[kk] = fmaf(Ck[kk][d], wv, p[kk]);
        }
        #pragma unroll
        for (int kk = 0; kk < 8; kk++) {
            #pragma unroll
            for (int o = 16; o; o >>= 1) p[kk] += __shfl_xor_sync(0xffffffffu, p[kk], o);
        }
        if (lane == 0) {
            float be = bias[e];
            #pragma unroll
            for (int kk = 0; kk < 8; kk++) {
                float diff = p[kk] + be - Ck[kk][e];
                sacc[kk] = fmaf(diff, diff, sacc[kk]);
            }
        }
    }
    if (lane == 0) {
        #pragma unroll
        for (int kk = 0; kk < 8; kk++) sred[warp][kk] = sacc[kk];
    }
    __syncthreads();
    if (tid < 8) {
        float s = 0.f;
        #pragma unroll
        for (int w = 0; w < 8; w++) s += sred[w][tid];
        g_s[k0 + tid] = s;
    }
}

// ---------------------------------------------------------------------------
// K3: fused SGEMM + argmin.
//   Block: 128 rows x all 2048 codes (looped in tiles of 128), 256 threads,
//   8x8 microtile per thread, fp32 FFMA, running (min, argmin) in registers.
//   score[n,k] = cbsq[k] - 2 * dot(means[n], C[k])
// ---------------------------------------------------------------------------
#define RT 128
#define CT 128
#define KT 8

__global__ __launch_bounds__(256, 2) void argmin_gemm(const float* __restrict__ Cb,
                                                      float* __restrict__ out_idx_f) {
    __shared__ float As[KT][RT];
    __shared__ float Bs[KT][CT];
    __shared__ float sq_s[CT];
    __shared__ float redv[RT][17];
    __shared__ int   redi[RT][17];

    int tid = threadIdx.x;
    int tx  = tid & 15;   // code dim
    int ty  = tid >> 4;   // row dim
    int row0 = blockIdx.x * RT;

    float minv[8];
    int   mini[8];
    #pragma unroll
    for (int r = 0; r < 8; r++) { minv[r] = 3.4e38f; mini[r] = 0; }

    const int ldr  = tid >> 1;          // 0..127
    const int koff = (tid & 1) * 4;     // 0 or 4

    for (int ct = 0; ct < KK; ct += CT) {
        if (tid < CT) sq_s[tid] = g_cbsq[ct + tid];

        float acc[8][8];
        #pragma unroll
        for (int r = 0; r < 8; r++)
            #pragma unroll
            for (int c = 0; c < 8; c++) acc[r][c] = 0.f;

        for (int d0 = 0; d0 < DD; d0 += KT) {
            // stage tiles (transposed into smem)
            float4 va = *(const float4*)&g_means[(row0 + ldr) * DD + d0 + koff];
            float4 vb = *(const float4*)&Cb[(ct + ldr) * DD + d0 + koff];
            As[koff + 0][ldr] = va.x; As[koff + 1][ldr] = va.y;
            As[koff + 2][ldr] = va.z; As[koff + 3][ldr] = va.w;
            Bs[koff + 0][ldr] = vb.x; Bs[koff + 1][ldr] = vb.y;
            Bs[koff + 2][ldr] = vb.z; Bs[koff + 3][ldr] = vb.w;
            __syncthreads();

            #pragma unroll
            for (int kkk = 0; kkk < KT; kkk++) {
                float a[8], b[8];
                *(float4*)(a)     = *(const float4*)&As[kkk][ty * 8];
                *(float4*)(a + 4) = *(const float4*)&As[kkk][ty * 8 + 4];
                *(float4*)(b)     = *(const float4*)&Bs[kkk][tx * 8];
                *(float4*)(b + 4) = *(const float4*)&Bs[kkk][tx * 8 + 4];
                #pragma unroll
                for (int r = 0; r < 8; r++)
                    #pragma unroll
                    for (int c = 0; c < 8; c++)
                        acc[r][c] = fmaf(a[r], b[c], acc[r][c]);
            }
            __syncthreads();
        }

        // fold tile into running argmin
        #pragma unroll
        for (int c = 0; c < 8; c++) {
            float q = sq_s[tx * 8 + c];
            int code = ct + tx * 8 + c;
            #pragma unroll
            for (int r = 0; r < 8; r++) {
                float s = fmaf(-2.0f, acc[r][c], q);
                if (s < minv[r]) { minv[r] = s; mini[r] = code; }
            }
        }
        __syncthreads();  // protect sq_s before next tile's rewrite
    }

    // cross-thread reduce: 16 tx candidates per row
    #pragma unroll
    for (int r = 0; r < 8; r++) {
        redv[ty * 8 + r][tx] = minv[r];
        redi[ty * 8 + r][tx] = mini[r];
    }
    __syncthreads();
    if (tid < RT) {
        float bv = redv[tid][0];
        int   bi = redi[tid][0];
        #pragma unroll
        for (int j = 1; j < 16; j++) {
            float v = redv[tid][j];
            int   i2 = redi[tid][j];
            if (v < bv || (v == bv && i2 < bi)) { bv = v; bi = i2; }
        }
        g_idx[row0 + tid] = bi;
        out_idx_f[row0 + tid] = (float)bi;
    }
}

// ---------------------------------------------------------------------------
// K4: gather word embeddings
// ---------------------------------------------------------------------------
__global__ void gather_kernel(const float4* __restrict__ Cb4, float4* __restrict__ out4) {
    int n = blockIdx.x;
    int idx = g_idx[n];
    out4[n * (DD / 4) + threadIdx.x] = Cb4[idx * (DD / 4) + threadIdx.x];
}

// ---------------------------------------------------------------------------
// K5: deterministic loss reduction: mean over B*G*D of per-row s[idx]
// ---------------------------------------------------------------------------
__global__ void loss_kernel(float* __restrict__ out_loss) {
    __shared__ float red[1024];
    float s = 0.f;
    for (int n = threadIdx.x; n < NROWS; n += 1024) s += g_s[g_idx[n]];
    red[threadIdx.x] = s;
    __syncthreads();
    for (int st = 512; st > 0; st >>= 1) {
        if (threadIdx.x < st) red[threadIdx.x] += red[threadIdx.x + st];
        __syncthreads();
    }
    if (threadIdx.x == 0)
        out_loss[0] = red[0] / (float)((long long)NROWS * DD);
}

// ---------------------------------------------------------------------------
extern "C" void kernel_launch(void* const* d_in, const int* in_sizes, int n_in,
                              void* d_out, int out_size) {
    // inputs: [0] char_tokens (unused), [1] char_embeddings, [2] word_codebook,
    //         [3] proj_w, [4] proj_b
    const float* E    = (const float*)d_in[1];
    const float* Cb   = (const float*)d_in[2];
    const float* W    = (const float*)d_in[3];
    const float* bias = (const float*)d_in[4];

    float* out      = (float*)d_out;
    float* out_idx  = out;                       // NROWS
    float* out_emb  = out + NROWS;               // NROWS*DD
    float* out_loss = out + NROWS + NROWS * DD;  // 1

    means_kernel<<<(NROWS * (DD / 4) + 255) / 256, 256>>>((const float4*)E);
    prep_kernel<<<KK / 8, 256>>>(Cb, W, bias);
    argmin_gemm<<<NROWS / RT, 256>>>(Cb, out_idx);
    gather_kernel<<<NROWS, DD / 4>>>((const float4*)Cb, (float4*)out_emb);
    loss_kernel<<<1, 1024>>>(out_loss);
}

// round 6
// speedup vs baseline: 2.3465x; 2.3462x over previous
#include <cuda_runtime.h>
#include <cuda_bf16.h>
#include <cstdint>

#define BB 16
#define LL 4096
#define DD 512
#define KK 2048
#define NROWS 32768

#define MT 128            // rows per CTA
#define NT 128            // codes per CTA
#define KC 32             // k elems per stage
#define NSTAGE (DD / KC)  // 16
#define NCTQ (KK / NT)    // 16

// ------------------------------------------------------------- device scratch
__device__ float          g_means[NROWS * DD];   // fp32 (exact rescore)
__device__ __nv_bfloat16  g_mh[NROWS * DD];      // means hi
__device__ __nv_bfloat16  g_ml[NROWS * DD];      // means lo
__device__ __nv_bfloat16  g_ch[KK * DD];         // codebook hi
__device__ __nv_bfloat16  g_cl[KK * DD];         // codebook lo
__device__ int            g_idx[NROWS];
__device__ float          g_cbsq[KK];
__device__ float          g_s[KK];
__device__ float4         g_part[NROWS * NCTQ];  // per (row, ctile): v1,i1,v2,i2

// ------------------------------------------------------------- PTX helpers
__device__ __forceinline__ uint32_t smem_u32(const void* p) {
    uint32_t a;
    asm("{ .reg .u64 t; cvta.to.shared.u64 t, %1; cvt.u32.u64 %0, t; }" : "=r"(a) : "l"(p));
    return a;
}
#define CP16(dst, src) \
    asm volatile("cp.async.cg.shared.global [%0], [%1], 16;" :: "r"(dst), "l"(src))
#define CP_COMMIT() asm volatile("cp.async.commit_group;" ::: "memory")
#define CP_WAIT1()  asm volatile("cp.async.wait_group 1;" ::: "memory")
#define LDSM_X4(r0, r1, r2, r3, addr)                                             \
    asm volatile("ldmatrix.sync.aligned.m8n8.x4.shared.b16 {%0,%1,%2,%3}, [%4];"  \
        : "=r"(r0), "=r"(r1), "=r"(r2), "=r"(r3) : "r"(addr))
__device__ __forceinline__ void mma_bf16(float* d, const uint32_t* a, const uint32_t* b) {
    asm volatile(
        "mma.sync.aligned.m16n8k16.row.col.f32.bf16.bf16.f32 "
        "{%0,%1,%2,%3}, {%4,%5,%6,%7}, {%8,%9}, {%0,%1,%2,%3};"
        : "+f"(d[0]), "+f"(d[1]), "+f"(d[2]), "+f"(d[3])
        : "r"(a[0]), "r"(a[1]), "r"(a[2]), "r"(a[3]), "r"(b[0]), "r"(b[1]));
}
__device__ __forceinline__ uint32_t pack_bf2(__nv_bfloat16 a, __nv_bfloat16 b) {
    return (uint32_t)__bfloat16_as_ushort(a) | ((uint32_t)__bfloat16_as_ushort(b) << 16);
}

// ------------------------------------------------------------- K1: means + split
__global__ void means_kernel(const float4* __restrict__ E) {
    int i = blockIdx.x * blockDim.x + threadIdx.x;
    const int D4 = DD / 4;
    if (i >= NROWS * D4) return;
    int row = i / D4, d4 = i - row * D4;
    float4 a = E[(2 * row) * D4 + d4];
    float4 b = E[(2 * row + 1) * D4 + d4];
    float4 m;
    m.x = 0.5f * (a.x + b.x); m.y = 0.5f * (a.y + b.y);
    m.z = 0.5f * (a.z + b.z); m.w = 0.5f * (a.w + b.w);
    ((float4*)g_means)[i] = m;
    __nv_bfloat16 hx = __float2bfloat16_rn(m.x), hy = __float2bfloat16_rn(m.y);
    __nv_bfloat16 hz = __float2bfloat16_rn(m.z), hw = __float2bfloat16_rn(m.w);
    uint2 hh = make_uint2(pack_bf2(hx, hy), pack_bf2(hz, hw));
    uint2 llo = make_uint2(
        pack_bf2(__float2bfloat16_rn(m.x - __bfloat162float(hx)),
                 __float2bfloat16_rn(m.y - __bfloat162float(hy))),
        pack_bf2(__float2bfloat16_rn(m.z - __bfloat162float(hz)),
                 __float2bfloat16_rn(m.w - __bfloat162float(hw))));
    ((uint2*)g_mh)[i] = hh;
    ((uint2*)g_ml)[i] = llo;
}

// ------------------------------------------------------------- K1b: codebook split
__global__ void cbsplit_kernel(const float4* __restrict__ Cb4) {
    int i = blockIdx.x * blockDim.x + threadIdx.x;
    if (i >= KK * DD / 4) return;
    float4 m = Cb4[i];
    __nv_bfloat16 hx = __float2bfloat16_rn(m.x), hy = __float2bfloat16_rn(m.y);
    __nv_bfloat16 hz = __float2bfloat16_rn(m.z), hw = __float2bfloat16_rn(m.w);
    ((uint2*)g_ch)[i] = make_uint2(pack_bf2(hx, hy), pack_bf2(hz, hw));
    ((uint2*)g_cl)[i] = make_uint2(
        pack_bf2(__float2bfloat16_rn(m.x - __bfloat162float(hx)),
                 __float2bfloat16_rn(m.y - __bfloat162float(hy))),
        pack_bf2(__float2bfloat16_rn(m.z - __bfloat162float(hz)),
                 __float2bfloat16_rn(m.w - __bfloat162float(hw))));
}

// ------------------------------------------------------------- K2: prep (cbsq + per-code loss)
__global__ __launch_bounds__(256) void prep_kernel(const float* __restrict__ Cb,
                                                   const float* __restrict__ W,
                                                   const float* __restrict__ bias) {
    __shared__ float Ck[8][DD];
    __shared__ float sred[8][8];
    int tid = threadIdx.x, warp = tid >> 5, lane = tid & 31;
    int k0 = blockIdx.x * 8;
    for (int i = tid; i < 8 * DD; i += 256) {
        int kk = i / DD, d = i - kk * DD;
        Ck[kk][d] = Cb[(k0 + kk) * DD + d];
    }
    __syncthreads();
    {
        float sq = 0.f;
        for (int d = lane; d < DD; d += 32) { float v = Ck[warp][d]; sq = fmaf(v, v, sq); }
        #pragma unroll
        for (int o = 16; o; o >>= 1) sq += __shfl_xor_sync(0xffffffffu, sq, o);
        if (lane == 0) g_cbsq[k0 + warp] = sq;
    }
    float sacc[8];
    #pragma unroll
    for (int kk = 0; kk < 8; kk++) sacc[kk] = 0.f;
    for (int e = warp; e < DD; e += 8) {
        float p[8];
        #pragma unroll
        for (int kk = 0; kk < 8; kk++) p[kk] = 0.f;
        for (int d = lane; d < DD; d += 32) {
            float wv = W[e * DD + d];
            #pragma unroll
            for (int kk = 0; kk < 8; kk++) p[kk] = fmaf(Ck[kk][d], wv, p[kk]);
        }
        #pragma unroll
        for (int kk = 0; kk < 8; kk++) {
            #pragma unroll
            for (int o = 16; o; o >>= 1) p[kk] += __shfl_xor_sync(0xffffffffu, p[kk], o);
        }
        if (lane == 0) {
            float be = bias[e];
            #pragma unroll
            for (int kk = 0; kk < 8; kk++) {
                float diff = p[kk] + be - Ck[kk][e];
                sacc[kk] = fmaf(diff, diff, sacc[kk]);
            }
        }
    }
    if (lane == 0) {
        #pragma unroll
        for (int kk = 0; kk < 8; kk++) sred[warp][kk] = sacc[kk];
    }
    __syncthreads();
    if (tid < 8) {
        float s = 0.f;
        #pragma unroll
        for (int w = 0; w < 8; w++) s += sred[w][tid];
        g_s[k0 + tid] = s;
    }
}

// ------------------------------------------------------------- K3: mma.sync bf16 3-split GEMM + top-2
// smem: [0..16K) smA buf0 | [16K..32K) smA buf1 | [32K..48K) smB buf0 | [48K..64K) smB buf1
//       [64K+1K = 65536..66048) cbsq tile.   red[] (8KB) aliases smA buf0 post-loop.
// Row layout (A and B): 128B = [32 bf16 hi | 32 bf16 lo], 16B chunks XOR-swizzled by row&7.
#define SMEM_GEMM 66048

__global__ __launch_bounds__(256, 1) void gemm_argmin() {
    extern __shared__ char smraw[];
    uint32_t sb = smem_u32(smraw);
    int tid = threadIdx.x;
    int lane = tid & 31, wid = tid >> 5;
    int wm = wid >> 2, wn = wid & 3;        // warp tile: rows wm*64, cols wn*32
    int row0 = blockIdx.x * MT;
    int ctbase = blockIdx.y * NT;

    const uint32_t smA[2] = { sb, sb + 16384 };
    const uint32_t smB[2] = { sb + 32768, sb + 49152 };
    float* cbs = (float*)(smraw + 65536);
    float4* red = (float4*)smraw;           // alias: used only after mainloop

    if (tid < NT) cbs[tid] = g_cbsq[ctbase + tid];

    // ldmatrix lane-invariants
    const int rA = lane & 15, cA = lane >> 4;                    // A: rows 0-15, k-chunk sel
    const int rB = (lane & 7) | ((lane >> 4) << 3);              // B: n row within 16
    const int cB = (lane >> 3) & 1;                              // B: k-chunk sel

    float acc[4][4][4];
    #pragma unroll
    for (int a = 0; a < 4; a++)
        #pragma unroll
        for (int b = 0; b < 4; b++)
            #pragma unroll
            for (int c = 0; c < 4; c++) acc[a][b][c] = 0.f;

    const int ldrow = tid >> 1, ldh = tid & 1;   // load slot: row 0-127, k-half

    auto issue = [&](int s, int b) {
        {
            const __nv_bfloat16* ph = g_mh + (size_t)(row0 + ldrow) * DD + s * KC + ldh * 16;
            const __nv_bfloat16* pl = g_ml + (size_t)(row0 + ldrow) * DD + s * KC + ldh * 16;
            uint32_t base = smA[b] + ldrow * 128;
            uint32_t x = (ldrow & 7) << 4;
            CP16(base + (((2 * ldh) << 4) ^ x), ph);
            CP16(base + (((2 * ldh + 1) << 4) ^ x), ph + 8);
            CP16(base + (((4 + 2 * ldh) << 4) ^ x), pl);
            CP16(base + (((5 + 2 * ldh) << 4) ^ x), pl + 8);
        }
        {
            const __nv_bfloat16* ph = g_ch + (size_t)(ctbase + ldrow) * DD + s * KC + ldh * 16;
            const __nv_bfloat16* pl = g_cl + (size_t)(ctbase + ldrow) * DD + s * KC + ldh * 16;
            uint32_t base = smB[b] + ldrow * 128;
            uint32_t x = (ldrow & 7) << 4;
            CP16(base + (((2 * ldh) << 4) ^ x), ph);
            CP16(base + (((2 * ldh + 1) << 4) ^ x), ph + 8);
            CP16(base + (((4 + 2 * ldh) << 4) ^ x), pl);
            CP16(base + (((5 + 2 * ldh) << 4) ^ x), pl + 8);
        }
    };

    issue(0, 0); CP_COMMIT();
    issue(1, 1); CP_COMMIT();

    for (int s = 0; s < NSTAGE; s++) {
        const int b = s & 1;
        CP_WAIT1();
        __syncthreads();

        #pragma unroll
        for (int kk = 0; kk < 2; kk++) {
            uint32_t ah[4][4], alo[4][4], bh[4][2], blo[4][2];
            #pragma unroll
            for (int mf = 0; mf < 4; mf++) {
                int row = wm * 64 + mf * 16 + rA;
                uint32_t ba = smA[b] + row * 128;
                uint32_t x = (row & 7) << 4;
                LDSM_X4(ah[mf][0], ah[mf][1], ah[mf][2], ah[mf][3],
                        ba + (((2 * kk + cA) << 4) ^ x));
                LDSM_X4(alo[mf][0], alo[mf][1], alo[mf][2], alo[mf][3],
                        ba + (((4 + 2 * kk + cA) << 4) ^ x));
            }
            #pragma unroll
            for (int np = 0; np < 2; np++) {
                int n = wn * 32 + np * 16 + rB;
                uint32_t bb = smB[b] + n * 128;
                uint32_t x = (n & 7) << 4;
                uint32_t t0, t1, t2, t3;
                LDSM_X4(t0, t1, t2, t3, bb + (((2 * kk + cB) << 4) ^ x));
                bh[2 * np][0] = t0; bh[2 * np][1] = t1;
                bh[2 * np + 1][0] = t2; bh[2 * np + 1][1] = t3;
                LDSM_X4(t0, t1, t2, t3, bb + (((4 + 2 * kk + cB) << 4) ^ x));
                blo[2 * np][0] = t0; blo[2 * np][1] = t1;
                blo[2 * np + 1][0] = t2; blo[2 * np + 1][1] = t3;
            }
            #pragma unroll
            for (int mf = 0; mf < 4; mf++)
                #pragma unroll
                for (int nf = 0; nf < 4; nf++) {
                    mma_bf16(acc[mf][nf], ah[mf], bh[nf]);
                    mma_bf16(acc[mf][nf], ah[mf], blo[nf]);
                    mma_bf16(acc[mf][nf], alo[mf], bh[nf]);
                }
        }
        __syncthreads();
        if (s + 2 < NSTAGE) issue(s + 2, b);
        CP_COMMIT();
    }

    // ---- epilogue: scores + per-row top-2 ----
    int g = lane >> 2, q = lane & 3;
    #pragma unroll
    for (int mf = 0; mf < 4; mf++) {
        #pragma unroll
        for (int half = 0; half < 2; half++) {
            int rloc = wm * 64 + mf * 16 + half * 8 + g;
            float v1 = 3.4e38f, v2 = 3.4e38f;
            int i1 = 0, i2 = 0;
            #pragma unroll
            for (int nf = 0; nf < 4; nf++) {
                #pragma unroll
                for (int j = 0; j < 2; j++) {
                    int cloc = wn * 32 + nf * 8 + 2 * q + j;
                    float sc = fmaf(-2.0f, acc[mf][nf][half * 2 + j], cbs[cloc]);
                    int code = ctbase + cloc;
                    if (sc < v1) { v2 = v1; i2 = i1; v1 = sc; i1 = code; }
                    else if (sc < v2) { v2 = sc; i2 = code; }
                }
            }
            #pragma unroll
            for (int o = 1; o <= 2; o <<= 1) {
                float w1 = __shfl_xor_sync(0xffffffffu, v1, o);
                int   j1 = __shfl_xor_sync(0xffffffffu, i1, o);
                float w2 = __shfl_xor_sync(0xffffffffu, v2, o);
                int   j2 = __shfl_xor_sync(0xffffffffu, i2, o);
                if (w1 < v1 || (w1 == v1 && j1 < i1)) { v2 = v1; i2 = i1; v1 = w1; i1 = j1; }
                else if (w1 < v2 || (w1 == v2 && j1 < i2)) { v2 = w1; i2 = j1; }
                if (w2 < v1 || (w2 == v1 && j2 < i1)) { v2 = v1; i2 = i1; v1 = w2; i1 = j2; }
                else if (w2 < v2 || (w2 == v2 && j2 < i2)) { v2 = w2; i2 = j2; }
            }
            if (q == 0)
                red[rloc * 4 + wn] =
                    make_float4(v1, __int_as_float(i1), v2, __int_as_float(i2));
        }
    }
    __syncthreads();
    if (tid < MT) {
        float v1 = 3.4e38f, v2 = 3.4e38f;
        int i1 = 0x7fffffff, i2 = 0x7fffffff;
        #pragma unroll
        for (int w = 0; w < 4; w++) {
            float4 p = red[tid * 4 + w];
            float w1 = p.x, w2 = p.z;
            int j1 = __float_as_int(p.y), j2 = __float_as_int(p.w);
            if (w1 < v1 || (w1 == v1 && j1 < i1)) { v2 = v1; i2 = i1; v1 = w1; i1 = j1; }
            else if (w1 < v2 || (w1 == v2 && j1 < i2)) { v2 = w1; i2 = j1; }
            if (w2 < v1 || (w2 == v1 && j2 < i1)) { v2 = v1; i2 = i1; v1 = w2; i1 = j2; }
            else if (w2 < v2 || (w2 == v2 && j2 < i2)) { v2 = w2; i2 = j2; }
        }
        g_part[(size_t)(row0 + tid) * NCTQ + blockIdx.y] =
            make_float4(v1, __int_as_float(i1), v2, __int_as_float(i2));
    }
}

// ------------------------------------------------------------- K4: combine + exact fp32 rescore
__global__ __launch_bounds__(256) void combine_kernel(const float* __restrict__ Cb,
                                                      float* __restrict__ out_idx_f) {
    int row = blockIdx.x * 8 + (threadIdx.x >> 5);
    int lane = threadIdx.x & 31;

    float v1 = 3.4e38f, v2 = 3.4e38f;
    int i1 = 0x7fffffff, i2 = 0x7fffffff;
    if (lane < NCTQ) {
        float4 p = g_part[(size_t)row * NCTQ + lane];
        v1 = p.x; i1 = __float_as_int(p.y);
        v2 = p.z; i2 = __float_as_int(p.w);
    }
    #pragma unroll
    for (int o = 16; o; o >>= 1) {
        float w1 = __shfl_xor_sync(0xffffffffu, v1, o);
        int   j1 = __shfl_xor_sync(0xffffffffu, i1, o);
        float w2 = __shfl_xor_sync(0xffffffffu, v2, o);
        int   j2 = __shfl_xor_sync(0xffffffffu, i2, o);
        if (w1 < v1 || (w1 == v1 && j1 < i1)) { v2 = v1; i2 = i1; v1 = w1; i1 = j1; }
        else if (w1 < v2 || (w1 == v2 && j1 < i2)) { v2 = w1; i2 = j1; }
        if (w2 < v1 || (w2 == v1 && j2 < i1)) { v2 = v1; i2 = i1; v1 = w2; i1 = j2; }
        else if (w2 < v2 || (w2 == v2 && j2 < i2)) { v2 = w2; i2 = j2; }
    }
    // exact fp32 rescore of the two leading candidates
    float d1 = 0.f, d2 = 0.f;
    const float* mrow = &g_means[(size_t)row * DD];
    const float* c1 = &Cb[(size_t)i1 * DD];
    const float* c2 = &Cb[(size_t)i2 * DD];
    for (int d = lane; d < DD; d += 32) {
        float m = mrow[d];
        d1 = fmaf(m, c1[d], d1);
        d2 = fmaf(m, c2[d], d2);
    }
    #pragma unroll
    for (int o = 16; o; o >>= 1) {
        d1 += __shfl_xor_sync(0xffffffffu, d1, o);
        d2 += __shfl_xor_sync(0xffffffffu, d2, o);
    }
    if (lane == 0) {
        float s1 = fmaf(-2.f, d1, g_cbsq[i1]);
        float s2 = fmaf(-2.f, d2, g_cbsq[i2]);
        int best = (s2 < s1 || (s2 == s1 && i2 < i1)) ? i2 : i1;
        g_idx[row] = best;
        out_idx_f[row] = (float)best;
    }
}

// ------------------------------------------------------------- K5: gather
__global__ void gather_kernel(const float4* __restrict__ Cb4, float4* __restrict__ out4) {
    int n = blockIdx.x;
    int idx = g_idx[n];
    out4[n * (DD / 4) + threadIdx.x] = Cb4[idx * (DD / 4) + threadIdx.x];
}

// ------------------------------------------------------------- K6: loss
__global__ void loss_kernel(float* __restrict__ out_loss) {
    __shared__ float red[1024];
    float s = 0.f;
    for (int n = threadIdx.x; n < NROWS; n += 1024) s += g_s[g_idx[n]];
    red[threadIdx.x] = s;
    __syncthreads();
    for (int st = 512; st > 0; st >>= 1) {
        if (threadIdx.x < st) red[threadIdx.x] += red[threadIdx.x + st];
        __syncthreads();
    }
    if (threadIdx.x == 0)
        out_loss[0] = red[0] / (float)((long long)NROWS * DD);
}

// -------------------------------------------------------------
extern "C" void kernel_launch(void* const* d_in, const int* in_sizes, int n_in,
                              void* d_out, int out_size) {
    const float* E    = (const float*)d_in[1];
    const float* Cb   = (const float*)d_in[2];
    const float* W    = (const float*)d_in[3];
    const float* bias = (const float*)d_in[4];

    float* out      = (float*)d_out;
    float* out_idx  = out;
    float* out_emb  = out + NROWS;
    float* out_loss = out + NROWS + NROWS * DD;

    cudaFuncSetAttribute(gemm_argmin, cudaFuncAttributeMaxDynamicSharedMemorySize, SMEM_GEMM);

    means_kernel<<<(NROWS * (DD / 4) + 255) / 256, 256>>>((const float4*)E);
    cbsplit_kernel<<<(KK * DD / 4 + 255) / 256, 256>>>((const float4*)Cb);
    prep_kernel<<<KK / 8, 256>>>(Cb, W, bias);
    gemm_argmin<<<dim3(NROWS / MT, NCTQ), 256, SMEM_GEMM>>>();
    combine_kernel<<<NROWS / 8, 256>>>(Cb, out_idx);
    gather_kernel<<<NROWS, DD / 4>>>((const float4*)Cb, (float4*)out_emb);
    loss_kernel<<<1, 1024>>>(out_loss);
}

// round 7
// speedup vs baseline: 2.7010x; 1.1511x over previous
#include <cuda_runtime.h>
#include <cuda_bf16.h>
#include <cstdint>

#define BB 16
#define LL 4096
#define DD 512
#define KK 2048
#define NROWS 32768

#define MT 128            // rows per CTA
#define NT 128            // codes per CTA
#define KC 32             // k elems per stage
#define NSTAGE (DD / KC)  // 16
#define NCTQ (KK / NT)    // 16

// ------------------------------------------------------------- device scratch
__device__ float          g_means[NROWS * DD];   // fp32 (exact rescore)
__device__ __nv_bfloat16  g_mh[NROWS * DD];      // means hi
__device__ __nv_bfloat16  g_ml[NROWS * DD];      // means lo
__device__ __nv_bfloat16  g_ch[KK * DD];         // codebook hi
__device__ __nv_bfloat16  g_cl[KK * DD];         // codebook lo
__device__ int            g_idx[NROWS];
__device__ float          g_cbsq[KK];
__device__ float          g_s[KK];
__device__ float4         g_part[NROWS * NCTQ];  // per (row, ctile): v1,i1,v2,i2

// ------------------------------------------------------------- PTX helpers
__device__ __forceinline__ uint32_t smem_u32(const void* p) {
    uint32_t a;
    asm("{ .reg .u64 t; cvta.to.shared.u64 t, %1; cvt.u32.u64 %0, t; }" : "=r"(a) : "l"(p));
    return a;
}
#define CP16(dst, src) \
    asm volatile("cp.async.cg.shared.global [%0], [%1], 16;" :: "r"(dst), "l"(src))
#define CP_COMMIT() asm volatile("cp.async.commit_group;" ::: "memory")
#define CP_WAIT1()  asm volatile("cp.async.wait_group 1;" ::: "memory")
#define LDSM_X4(r0, r1, r2, r3, addr)                                             \
    asm volatile("ldmatrix.sync.aligned.m8n8.x4.shared.b16 {%0,%1,%2,%3}, [%4];"  \
        : "=r"(r0), "=r"(r1), "=r"(r2), "=r"(r3) : "r"(addr))
__device__ __forceinline__ void mma_bf16(float* d, const uint32_t* a, const uint32_t* b) {
    asm volatile(
        "mma.sync.aligned.m16n8k16.row.col.f32.bf16.bf16.f32 "
        "{%0,%1,%2,%3}, {%4,%5,%6,%7}, {%8,%9}, {%0,%1,%2,%3};"
        : "+f"(d[0]), "+f"(d[1]), "+f"(d[2]), "+f"(d[3])
        : "r"(a[0]), "r"(a[1]), "r"(a[2]), "r"(a[3]), "r"(b[0]), "r"(b[1]));
}
__device__ __forceinline__ uint32_t pack_bf2(__nv_bfloat16 a, __nv_bfloat16 b) {
    return (uint32_t)__bfloat16_as_ushort(a) | ((uint32_t)__bfloat16_as_ushort(b) << 16);
}

// ------------------------------------------------------------- K1: means + split
__global__ void means_kernel(const float4* __restrict__ E) {
    int i = blockIdx.x * blockDim.x + threadIdx.x;
    const int D4 = DD / 4;
    if (i >= NROWS * D4) return;
    int row = i / D4, d4 = i - row * D4;
    float4 a = E[(2 * row) * D4 + d4];
    float4 b = E[(2 * row + 1) * D4 + d4];
    float4 m;
    m.x = 0.5f * (a.x + b.x); m.y = 0.5f * (a.y + b.y);
    m.z = 0.5f * (a.z + b.z); m.w = 0.5f * (a.w + b.w);
    ((float4*)g_means)[i] = m;
    __nv_bfloat16 hx = __float2bfloat16_rn(m.x), hy = __float2bfloat16_rn(m.y);
    __nv_bfloat16 hz = __float2bfloat16_rn(m.z), hw = __float2bfloat16_rn(m.w);
    ((uint2*)g_mh)[i] = make_uint2(pack_bf2(hx, hy), pack_bf2(hz, hw));
    ((uint2*)g_ml)[i] = make_uint2(
        pack_bf2(__float2bfloat16_rn(m.x - __bfloat162float(hx)),
                 __float2bfloat16_rn(m.y - __bfloat162float(hy))),
        pack_bf2(__float2bfloat16_rn(m.z - __bfloat162float(hz)),
                 __float2bfloat16_rn(m.w - __bfloat162float(hw))));
}

// ------------------------------------------------------------- K1b: codebook split
__global__ void cbsplit_kernel(const float4* __restrict__ Cb4) {
    int i = blockIdx.x * blockDim.x + threadIdx.x;
    if (i >= KK * DD / 4) return;
    float4 m = Cb4[i];
    __nv_bfloat16 hx = __float2bfloat16_rn(m.x), hy = __float2bfloat16_rn(m.y);
    __nv_bfloat16 hz = __float2bfloat16_rn(m.z), hw = __float2bfloat16_rn(m.w);
    ((uint2*)g_ch)[i] = make_uint2(pack_bf2(hx, hy), pack_bf2(hz, hw));
    ((uint2*)g_cl)[i] = make_uint2(
        pack_bf2(__float2bfloat16_rn(m.x - __bfloat162float(hx)),
                 __float2bfloat16_rn(m.y - __bfloat162float(hy))),
        pack_bf2(__float2bfloat16_rn(m.z - __bfloat162float(hz)),
                 __float2bfloat16_rn(m.w - __bfloat162float(hw))));
}

// ------------------------------------------------------------- K2: prep (cbsq + per-code loss)
__global__ __launch_bounds__(256) void prep_kernel(const float* __restrict__ Cb,
                                                   const float* __restrict__ W,
                                                   const float* __restrict__ bias) {
    __shared__ float Ck[8][DD];
    __shared__ float sred[8][8];
    int tid = threadIdx.x, warp = tid >> 5, lane = tid & 31;
    int k0 = blockIdx.x * 8;
    for (int i = tid; i < 8 * DD; i += 256) {
        int kk = i / DD, d = i - kk * DD;
        Ck[kk][d] = Cb[(k0 + kk) * DD + d];
    }
    __syncthreads();
    {
        float sq = 0.f;
        for (int d = lane; d < DD; d += 32) { float v = Ck[warp][d]; sq = fmaf(v, v, sq); }
        #pragma unroll
        for (int o = 16; o; o >>= 1) sq += __shfl_xor_sync(0xffffffffu, sq, o);
        if (lane == 0) g_cbsq[k0 + warp] = sq;
    }
    float sacc[8];
    #pragma unroll
    for (int kk = 0; kk < 8; kk++) sacc[kk] = 0.f;
    for (int e = warp; e < DD; e += 8) {
        float p[8];
        #pragma unroll
        for (int kk = 0; kk < 8; kk++) p[kk] = 0.f;
        for (int d = lane; d < DD; d += 32) {
            float wv = W[e * DD + d];
            #pragma unroll
            for (int kk = 0; kk < 8; kk++) p[kk] = fmaf(Ck[kk][d], wv, p[kk]);
        }
        #pragma unroll
        for (int kk = 0; kk < 8; kk++) {
            #pragma unroll
            for (int o = 16; o; o >>= 1) p[kk] += __shfl_xor_sync(0xffffffffu, p[kk], o);
        }
        if (lane == 0) {
            float be = bias[e];
            #pragma unroll
            for (int kk = 0; kk < 8; kk++) {
                float diff = p[kk] + be - Ck[kk][e];
                sacc[kk] = fmaf(diff, diff, sacc[kk]);
            }
        }
    }
    if (lane == 0) {
        #pragma unroll
        for (int kk = 0; kk < 8; kk++) sred[warp][kk] = sacc[kk];
    }
    __syncthreads();
    if (tid < 8) {
        float s = 0.f;
        #pragma unroll
        for (int w = 0; w < 8; w++) s += sred[w][tid];
        g_s[k0 + tid] = s;
    }
}

// ------------------------------------------------------------- K3: mma.sync bf16 3-split GEMM + top-2
// 512 threads, 16 warps (4x4), warp tile 32x32. Double-buffered cp.async.
// Row layout (A and B): 128B = [32 bf16 hi | 32 bf16 lo], 16B chunks XOR-swizzled by row&7.
#define SMEM_GEMM 66048

__global__ __launch_bounds__(512, 1) void gemm_argmin() {
    extern __shared__ char smraw[];
    uint32_t sb = smem_u32(smraw);
    int tid = threadIdx.x;
    int lane = tid & 31, wid = tid >> 5;
    int wm = wid >> 2, wn = wid & 3;        // warp tile: rows wm*32, cols wn*32
    int row0 = blockIdx.x * MT;
    int ctbase = blockIdx.y * NT;

    const uint32_t smA[2] = { sb, sb + 16384 };
    const uint32_t smB[2] = { sb + 32768, sb + 49152 };
    float* cbs = (float*)(smraw + 65536);
    float4* red = (float4*)smraw;           // alias: used only after mainloop

    if (tid < NT) cbs[tid] = g_cbsq[ctbase + tid];

    // ldmatrix lane-invariants
    const int rA = lane & 15, cA = lane >> 4;        // A: rows 0-15, k-chunk sel
    const int rB = (lane & 7) | ((lane >> 4) << 3);  // B: n row within 16
    const int cB = (lane >> 3) & 1;                  // B: k-chunk sel

    float acc[2][4][4];
    #pragma unroll
    for (int a = 0; a < 2; a++)
        #pragma unroll
        for (int b = 0; b < 4; b++)
            #pragma unroll
            for (int c = 0; c < 4; c++) acc[a][b][c] = 0.f;

    const int ldrow = tid >> 2, ldc = tid & 3;   // load slot: row 0-127, 16B chunk 0-3

    auto issue = [&](int s, int b) {
        uint32_t x = (ldrow & 7) << 4;
        {
            const __nv_bfloat16* ph = g_mh + (size_t)(row0 + ldrow) * DD + s * KC + ldc * 8;
            const __nv_bfloat16* pl = g_ml + (size_t)(row0 + ldrow) * DD + s * KC + ldc * 8;
            uint32_t base = smA[b] + ldrow * 128;
            CP16(base + ((ldc << 4) ^ x), ph);
            CP16(base + (((4 + ldc) << 4) ^ x), pl);
        }
        {
            const __nv_bfloat16* ph = g_ch + (size_t)(ctbase + ldrow) * DD + s * KC + ldc * 8;
            const __nv_bfloat16* pl = g_cl + (size_t)(ctbase + ldrow) * DD + s * KC + ldc * 8;
            uint32_t base = smB[b] + ldrow * 128;
            CP16(base + ((ldc << 4) ^ x), ph);
            CP16(base + (((4 + ldc) << 4) ^ x), pl);
        }
    };

    issue(0, 0); CP_COMMIT();
    issue(1, 1); CP_COMMIT();

    for (int s = 0; s < NSTAGE; s++) {
        const int b = s & 1;
        CP_WAIT1();
        __syncthreads();

        #pragma unroll
        for (int kk = 0; kk < 2; kk++) {
            uint32_t ah[2][4], alo[2][4], bh[4][2], blo[4][2];
            #pragma unroll
            for (int mf = 0; mf < 2; mf++) {
                int row = wm * 32 + mf * 16 + rA;
                uint32_t ba = smA[b] + row * 128;
                uint32_t x = (row & 7) << 4;
                LDSM_X4(ah[mf][0], ah[mf][1], ah[mf][2], ah[mf][3],
                        ba + (((2 * kk + cA) << 4) ^ x));
                LDSM_X4(alo[mf][0], alo[mf][1], alo[mf][2], alo[mf][3],
                        ba + (((4 + 2 * kk + cA) << 4) ^ x));
            }
            #pragma unroll
            for (int np = 0; np < 2; np++) {
                int n = wn * 32 + np * 16 + rB;
                uint32_t bb = smB[b] + n * 128;
                uint32_t x = (n & 7) << 4;
                uint32_t t0, t1, t2, t3;
                LDSM_X4(t0, t1, t2, t3, bb + (((2 * kk + cB) << 4) ^ x));
                bh[2 * np][0] = t0; bh[2 * np][1] = t1;
                bh[2 * np + 1][0] = t2; bh[2 * np + 1][1] = t3;
                LDSM_X4(t0, t1, t2, t3, bb + (((4 + 2 * kk + cB) << 4) ^ x));
                blo[2 * np][0] = t0; blo[2 * np][1] = t1;
                blo[2 * np + 1][0] = t2; blo[2 * np + 1][1] = t3;
            }
            // independent-MMA ordering: all hh, then all hl, then all lh
            #pragma unroll
            for (int mf = 0; mf < 2; mf++)
                #pragma unroll
                for (int nf = 0; nf < 4; nf++)
                    mma_bf16(acc[mf][nf], ah[mf], bh[nf]);
            #pragma unroll
            for (int mf = 0; mf < 2; mf++)
                #pragma unroll
                for (int nf = 0; nf < 4; nf++)
                    mma_bf16(acc[mf][nf], ah[mf], blo[nf]);
            #pragma unroll
            for (int mf = 0; mf < 2; mf++)
                #pragma unroll
                for (int nf = 0; nf < 4; nf++)
                    mma_bf16(acc[mf][nf], alo[mf], bh[nf]);
        }
        __syncthreads();
        if (s + 2 < NSTAGE) issue(s + 2, b);
        CP_COMMIT();
    }
    __syncthreads();   // before aliasing smA as red[]

    // ---- epilogue: scores + per-row top-2 ----
    int g = lane >> 2, q = lane & 3;
    #pragma unroll
    for (int mf = 0; mf < 2; mf++) {
        #pragma unroll
        for (int half = 0; half < 2; half++) {
            int rloc = wm * 32 + mf * 16 + half * 8 + g;
            float v1 = 3.4e38f, v2 = 3.4e38f;
            int i1 = 0, i2 = 0;
            #pragma unroll
            for (int nf = 0; nf < 4; nf++) {
                #pragma unroll
                for (int j = 0; j < 2; j++) {
                    int cloc = wn * 32 + nf * 8 + 2 * q + j;
                    float sc = fmaf(-2.0f, acc[mf][nf][half * 2 + j], cbs[cloc]);
                    int code = ctbase + cloc;
                    if (sc < v1) { v2 = v1; i2 = i1; v1 = sc; i1 = code; }
                    else if (sc < v2) { v2 = sc; i2 = code; }
                }
            }
            #pragma unroll
            for (int o = 1; o <= 2; o <<= 1) {
                float w1 = __shfl_xor_sync(0xffffffffu, v1, o);
                int   j1 = __shfl_xor_sync(0xffffffffu, i1, o);
                float w2 = __shfl_xor_sync(0xffffffffu, v2, o);
                int   j2 = __shfl_xor_sync(0xffffffffu, i2, o);
                if (w1 < v1 || (w1 == v1 && j1 < i1)) { v2 = v1; i2 = i1; v1 = w1; i1 = j1; }
                else if (w1 < v2 || (w1 == v2 && j1 < i2)) { v2 = w1; i2 = j1; }
                if (w2 < v1 || (w2 == v1 && j2 < i1)) { v2 = v1; i2 = i1; v1 = w2; i1 = j2; }
                else if (w2 < v2 || (w2 == v2 && j2 < i2)) { v2 = w2; i2 = j2; }
            }
            if (q == 0)
                red[rloc * 4 + wn] =
                    make_float4(v1, __int_as_float(i1), v2, __int_as_float(i2));
        }
    }
    __syncthreads();
    if (tid < MT) {
        float v1 = 3.4e38f, v2 = 3.4e38f;
        int i1 = 0x7fffffff, i2 = 0x7fffffff;
        #pragma unroll
        for (int w = 0; w < 4; w++) {
            float4 p = red[tid * 4 + w];
            float w1 = p.x, w2 = p.z;
            int j1 = __float_as_int(p.y), j2 = __float_as_int(p.w);
            if (w1 < v1 || (w1 == v1 && j1 < i1)) { v2 = v1; i2 = i1; v1 = w1; i1 = j1; }
            else if (w1 < v2 || (w1 == v2 && j1 < i2)) { v2 = w1; i2 = j1; }
            if (w2 < v1 || (w2 == v1 && j2 < i1)) { v2 = v1; i2 = i1; v1 = w2; i1 = j2; }
            else if (w2 < v2 || (w2 == v2 && j2 < i2)) { v2 = w2; i2 = j2; }
        }
        g_part[(size_t)(row0 + tid) * NCTQ + blockIdx.y] =
            make_float4(v1, __int_as_float(i1), v2, __int_as_float(i2));
    }
}

// ------------------------------------------------------------- K4: combine + exact rescore + gather
__global__ __launch_bounds__(256) void combine_kernel(const float* __restrict__ Cb,
                                                      float* __restrict__ out_idx_f,
                                                      float4* __restrict__ out_emb4) {
    int row = blockIdx.x * 8 + (threadIdx.x >> 5);
    int lane = threadIdx.x & 31;

    float v1 = 3.4e38f, v2 = 3.4e38f;
    int i1 = 0x7fffffff, i2 = 0x7fffffff;
    if (lane < NCTQ) {
        float4 p = g_part[(size_t)row * NCTQ + lane];
        v1 = p.x; i1 = __float_as_int(p.y);
        v2 = p.z; i2 = __float_as_int(p.w);
    }
    #pragma unroll
    for (int o = 16; o; o >>= 1) {
        float w1 = __shfl_xor_sync(0xffffffffu, v1, o);
        int   j1 = __shfl_xor_sync(0xffffffffu, i1, o);
        float w2 = __shfl_xor_sync(0xffffffffu, v2, o);
        int   j2 = __shfl_xor_sync(0xffffffffu, i2, o);
        if (w1 < v1 || (w1 == v1 && j1 < i1)) { v2 = v1; i2 = i1; v1 = w1; i1 = j1; }
        else if (w1 < v2 || (w1 == v2 && j1 < i2)) { v2 = w1; i2 = j1; }
        if (w2 < v1 || (w2 == v1 && j2 < i1)) { v2 = v1; i2 = i1; v1 = w2; i1 = j2; }
        else if (w2 < v2 || (w2 == v2 && j2 < i2)) { v2 = w2; i2 = j2; }
    }
    // exact fp32 rescore of the two leading candidates
    float d1 = 0.f, d2 = 0.f;
    const float* mrow = &g_means[(size_t)row * DD];
    const float* c1 = &Cb[(size_t)i1 * DD];
    const float* c2 = &Cb[(size_t)i2 * DD];
    for (int d = lane; d < DD; d += 32) {
        float m = mrow[d];
        d1 = fmaf(m, c1[d], d1);
        d2 = fmaf(m, c2[d], d2);
    }
    #pragma unroll
    for (int o = 16; o; o >>= 1) {
        d1 += __shfl_xor_sync(0xffffffffu, d1, o);
        d2 += __shfl_xor_sync(0xffffffffu, d2, o);
    }
    float s1 = fmaf(-2.f, d1, g_cbsq[i1]);
    float s2 = fmaf(-2.f, d2, g_cbsq[i2]);
    int best = (s2 < s1 || (s2 == s1 && i2 < i1)) ? i2 : i1;
    if (lane == 0) {
        g_idx[row] = best;
        out_idx_f[row] = (float)best;
    }
    // fused gather: write winner's embedding (rows hot in L2 from rescore)
    const float4* src = (const float4*)&Cb[(size_t)best * DD];
    float4* dst = out_emb4 + (size_t)row * (DD / 4);
    #pragma unroll
    for (int j = 0; j < 4; j++)
        dst[lane + 32 * j] = src[lane + 32 * j];
}

// ------------------------------------------------------------- K5: loss
__global__ void loss_kernel(float* __restrict__ out_loss) {
    __shared__ float red[1024];
    float s = 0.f;
    for (int n = threadIdx.x; n < NROWS; n += 1024) s += g_s[g_idx[n]];
    red[threadIdx.x] = s;
    __syncthreads();
    for (int st = 512; st > 0; st >>= 1) {
        if (threadIdx.x < st) red[threadIdx.x] += red[threadIdx.x + st];
        __syncthreads();
    }
    if (threadIdx.x == 0)
        out_loss[0] = red[0] / (float)((long long)NROWS * DD);
}

// -------------------------------------------------------------
extern "C" void kernel_launch(void* const* d_in, const int* in_sizes, int n_in,
                              void* d_out, int out_size) {
    const float* E    = (const float*)d_in[1];
    const float* Cb   = (const float*)d_in[2];
    const float* W    = (const float*)d_in[3];
    const float* bias = (const float*)d_in[4];

    float* out      = (float*)d_out;
    float* out_idx  = out;
    float* out_emb  = out + NROWS;
    float* out_loss = out + NROWS + NROWS * DD;

    cudaFuncSetAttribute(gemm_argmin, cudaFuncAttributeMaxDynamicSharedMemorySize, SMEM_GEMM);

    means_kernel<<<(NROWS * (DD / 4) + 255) / 256, 256>>>((const float4*)E);
    cbsplit_kernel<<<(KK * DD / 4 + 255) / 256, 256>>>((const float4*)Cb);
    prep_kernel<<<KK / 8, 256>>>(Cb, W, bias);
    gemm_argmin<<<dim3(NROWS / MT, NCTQ), 512, SMEM_GEMM>>>();
    combine_kernel<<<NROWS / 8, 256>>>(Cb, out_idx, (float4*)out_emb);
    loss_kernel<<<1, 1024>>>(out_loss);
}

// round 8
// speedup vs baseline: 3.2990x; 1.2214x over previous
#include <cuda_runtime.h>
#include <cuda_fp16.h>
#include <cstdint>

#define BB 16
#define LL 4096
#define DD 512
#define KK 2048
#define NROWS 32768

#define MT 128            // rows per CTA
#define NT 128            // codes per CTA
#define KC 32             // k elems per stage
#define NSTAGE (DD / KC)  // 16
#define NCTQ (KK / NT)    // 16
#define CBSCALE 2048.0f   // codebook scale: argmin-invariant, keeps fp16 lo normal

// ------------------------------------------------------------- device scratch
__device__ float   g_means[NROWS * DD];   // fp32 (exact rescore)
__device__ __half  g_mh[NROWS * DD];      // means hi (fp16)
__device__ __half  g_ch[KK * DD];         // codebook*2048 hi
__device__ __half  g_cl[KK * DD];         // codebook*2048 lo
__device__ int     g_idx[NROWS];
__device__ float   g_cbsq[KK];
__device__ float   g_s[KK];
__device__ float4  g_part[NROWS * NCTQ];  // per (row, ctile): v1,i1,v2,i2

// ------------------------------------------------------------- PTX helpers
__device__ __forceinline__ uint32_t smem_u32(const void* p) {
    uint32_t a;
    asm("{ .reg .u64 t; cvta.to.shared.u64 t, %1; cvt.u32.u64 %0, t; }" : "=r"(a) : "l"(p));
    return a;
}
#define CP16(dst, src) \
    asm volatile("cp.async.cg.shared.global [%0], [%1], 16;" :: "r"(dst), "l"(src))
#define CP_COMMIT() asm volatile("cp.async.commit_group;" ::: "memory")
#define CP_WAIT1()  asm volatile("cp.async.wait_group 1;" ::: "memory")
#define LDSM_X4(r0, r1, r2, r3, addr)                                             \
    asm volatile("ldmatrix.sync.aligned.m8n8.x4.shared.b16 {%0,%1,%2,%3}, [%4];"  \
        : "=r"(r0), "=r"(r1), "=r"(r2), "=r"(r3) : "r"(addr))
__device__ __forceinline__ void mma_f16(float* d, const uint32_t* a, const uint32_t* b) {
    asm volatile(
        "mma.sync.aligned.m16n8k16.row.col.f32.f16.f16.f32 "
        "{%0,%1,%2,%3}, {%4,%5,%6,%7}, {%8,%9}, {%0,%1,%2,%3};"
        : "+f"(d[0]), "+f"(d[1]), "+f"(d[2]), "+f"(d[3])
        : "r"(a[0]), "r"(a[1]), "r"(a[2]), "r"(a[3]), "r"(b[0]), "r"(b[1]));
}
__device__ __forceinline__ uint32_t pack_h2(__half a, __half b) {
    return (uint32_t)__half_as_ushort(a) | ((uint32_t)__half_as_ushort(b) << 16);
}

// ------------------------------------------------------------- K1: means + fp16 hi
__global__ void means_kernel(const float4* __restrict__ E) {
    int i = blockIdx.x * blockDim.x + threadIdx.x;
    const int D4 = DD / 4;
    if (i >= NROWS * D4) return;
    int row = i / D4, d4 = i - row * D4;
    float4 a = E[(2 * row) * D4 + d4];
    float4 b = E[(2 * row + 1) * D4 + d4];
    float4 m;
    m.x = 0.5f * (a.x + b.x); m.y = 0.5f * (a.y + b.y);
    m.z = 0.5f * (a.z + b.z); m.w = 0.5f * (a.w + b.w);
    ((float4*)g_means)[i] = m;
    ((uint2*)g_mh)[i] = make_uint2(
        pack_h2(__float2half_rn(m.x), __float2half_rn(m.y)),
        pack_h2(__float2half_rn(m.z), __float2half_rn(m.w)));
}

// ------------------------------------------------------------- K1b: codebook scale+split
__global__ void cbsplit_kernel(const float4* __restrict__ Cb4) {
    int i = blockIdx.x * blockDim.x + threadIdx.x;
    if (i >= KK * DD / 4) return;
    float4 m = Cb4[i];
    m.x *= CBSCALE; m.y *= CBSCALE; m.z *= CBSCALE; m.w *= CBSCALE;
    __half hx = __float2half_rn(m.x), hy = __float2half_rn(m.y);
    __half hz = __float2half_rn(m.z), hw = __float2half_rn(m.w);
    ((uint2*)g_ch)[i] = make_uint2(pack_h2(hx, hy), pack_h2(hz, hw));
    ((uint2*)g_cl)[i] = make_uint2(
        pack_h2(__float2half_rn(m.x - __half2float(hx)),
                __float2half_rn(m.y - __half2float(hy))),
        pack_h2(__float2half_rn(m.z - __half2float(hz)),
                __float2half_rn(m.w - __half2float(hw))));
}

// ------------------------------------------------------------- K2: prep (cbsq + per-code loss)
__global__ __launch_bounds__(256) void prep_kernel(const float* __restrict__ Cb,
                                                   const float* __restrict__ W,
                                                   const float* __restrict__ bias) {
    __shared__ float Ck[8][DD];
    __shared__ float sred[8][8];
    int tid = threadIdx.x, warp = tid >> 5, lane = tid & 31;
    int k0 = blockIdx.x * 8;
    for (int i = tid; i < 8 * DD; i += 256) {
        int kk = i / DD, d = i - kk * DD;
        Ck[kk][d] = Cb[(k0 + kk) * DD + d];
    }
    __syncthreads();
    {
        float sq = 0.f;
        for (int d = lane; d < DD; d += 32) { float v = Ck[warp][d]; sq = fmaf(v, v, sq); }
        #pragma unroll
        for (int o = 16; o; o >>= 1) sq += __shfl_xor_sync(0xffffffffu, sq, o);
        if (lane == 0) g_cbsq[k0 + warp] = sq;
    }
    float sacc[8];
    #pragma unroll
    for (int kk = 0; kk < 8; kk++) sacc[kk] = 0.f;
    for (int e = warp; e < DD; e += 8) {
        float p[8];
        #pragma unroll
        for (int kk = 0; kk < 8; kk++) p[kk] = 0.f;
        for (int d = lane; d < DD; d += 32) {
            float wv = W[e * DD + d];
            #pragma unroll
            for (int kk = 0; kk < 8; kk++) p[kk] = fmaf(Ck[kk][d], wv, p[kk]);
        }
        #pragma unroll
        for (int kk = 0; kk < 8; kk++) {
            #pragma unroll
            for (int o = 16; o; o >>= 1) p[kk] += __shfl_xor_sync(0xffffffffu, p[kk], o);
        }
        if (lane == 0) {
            float be = bias[e];
            #pragma unroll
            for (int kk = 0; kk < 8; kk++) {
                float diff = p[kk] + be - Ck[kk][e];
                sacc[kk] = fmaf(diff, diff, sacc[kk]);
            }
        }
    }
    if (lane == 0) {
        #pragma unroll
        for (int kk = 0; kk < 8; kk++) sred[warp][kk] = sacc[kk];
    }
    __syncthreads();
    if (tid < 8) {
        float s = 0.f;
        #pragma unroll
        for (int w = 0; w < 8; w++) s += sred[w][tid];
        g_s[k0 + tid] = s;
    }
}

// ------------------------------------------------------------- K3: fp16 2-MMA split GEMM + top-2
// 512 threads, 16 warps (4x4), warp tile 32x32. Double-buffered cp.async.
// A rows: 128B stride, hi in logical chunks 0-3, XOR-swizzled by row&7 (spills into 4-7).
// B rows: 128B = [32 fp16 hi | 32 fp16 lo], chunks XOR-swizzled by row&7.
#define SMEM_GEMM 66048

__global__ __launch_bounds__(512, 1) void gemm_argmin() {
    extern __shared__ char smraw[];
    uint32_t sb = smem_u32(smraw);
    int tid = threadIdx.x;
    int lane = tid & 31, wid = tid >> 5;
    int wm = wid >> 2, wn = wid & 3;        // warp tile: rows wm*32, cols wn*32
    int row0 = blockIdx.x * MT;
    int ctbase = blockIdx.y * NT;

    const uint32_t smA[2] = { sb, sb + 16384 };
    const uint32_t smB[2] = { sb + 32768, sb + 49152 };
    float* cbs = (float*)(smraw + 65536);
    float4* red = (float4*)smraw;           // alias: used only after mainloop

    if (tid < NT) cbs[tid] = g_cbsq[ctbase + tid] * CBSCALE;

    // ldmatrix lane-invariants
    const int rA = lane & 15, cA = lane >> 4;        // A: rows 0-15, k-chunk sel
    const int rB = (lane & 7) | ((lane >> 4) << 3);  // B: n row within 16
    const int cB = (lane >> 3) & 1;                  // B: k-chunk sel

    float acc[2][4][4];
    #pragma unroll
    for (int a = 0; a < 2; a++)
        #pragma unroll
        for (int b = 0; b < 4; b++)
            #pragma unroll
            for (int c = 0; c < 4; c++) acc[a][b][c] = 0.f;

    const int ldrow = tid >> 2, ldc = tid & 3;   // load slot: row 0-127, 16B chunk 0-3

    auto issue = [&](int s, int b) {
        uint32_t x = (ldrow & 7) << 4;
        {
            const __half* ph = g_mh + (size_t)(row0 + ldrow) * DD + s * KC + ldc * 8;
            CP16(smA[b] + ldrow * 128 + ((ldc << 4) ^ x), ph);
        }
        {
            const __half* ph = g_ch + (size_t)(ctbase + ldrow) * DD + s * KC + ldc * 8;
            const __half* pl = g_cl + (size_t)(ctbase + ldrow) * DD + s * KC + ldc * 8;
            uint32_t base = smB[b] + ldrow * 128;
            CP16(base + ((ldc << 4) ^ x), ph);
            CP16(base + (((4 + ldc) << 4) ^ x), pl);
        }
    };

    issue(0, 0); CP_COMMIT();
    issue(1, 1); CP_COMMIT();

    for (int s = 0; s < NSTAGE; s++) {
        const int b = s & 1;
        CP_WAIT1();
        __syncthreads();

        #pragma unroll
        for (int kk = 0; kk < 2; kk++) {
            uint32_t ah[2][4], bh[4][2], blo[4][2];
            #pragma unroll
            for (int mf = 0; mf < 2; mf++) {
                int row = wm * 32 + mf * 16 + rA;
                uint32_t ba = smA[b] + row * 128;
                uint32_t x = (row & 7) << 4;
                LDSM_X4(ah[mf][0], ah[mf][1], ah[mf][2], ah[mf][3],
                        ba + (((2 * kk + cA) << 4) ^ x));
            }
            #pragma unroll
            for (int np = 0; np < 2; np++) {
                int n = wn * 32 + np * 16 + rB;
                uint32_t bb = smB[b] + n * 128;
                uint32_t x = (n & 7) << 4;
                uint32_t t0, t1, t2, t3;
                LDSM_X4(t0, t1, t2, t3, bb + (((2 * kk + cB) << 4) ^ x));
                bh[2 * np][0] = t0; bh[2 * np][1] = t1;
                bh[2 * np + 1][0] = t2; bh[2 * np + 1][1] = t3;
                LDSM_X4(t0, t1, t2, t3, bb + (((4 + 2 * kk + cB) << 4) ^ x));
                blo[2 * np][0] = t0; blo[2 * np][1] = t1;
                blo[2 * np + 1][0] = t2; blo[2 * np + 1][1] = t3;
            }
            // 2-MMA split: hh then hl; 16 independent accumulators between reuses
            #pragma unroll
            for (int mf = 0; mf < 2; mf++)
                #pragma unroll
                for (int nf = 0; nf < 4; nf++)
                    mma_f16(acc[mf][nf], ah[mf], bh[nf]);
            #pragma unroll
            for (int mf = 0; mf < 2; mf++)
                #pragma unroll
                for (int nf = 0; nf < 4; nf++)
                    mma_f16(acc[mf][nf], ah[mf], blo[nf]);
        }
        __syncthreads();
        if (s + 2 < NSTAGE) issue(s + 2, b);
        CP_COMMIT();
    }
    __syncthreads();   // before aliasing smA as red[]

    // ---- epilogue: scores + per-row top-2 ----
    int g = lane >> 2, q = lane & 3;
    #pragma unroll
    for (int mf = 0; mf < 2; mf++) {
        #pragma unroll
        for (int half = 0; half < 2; half++) {
            int rloc = wm * 32 + mf * 16 + half * 8 + g;
            float v1 = 3.4e38f, v2 = 3.4e38f;
            int i1 = 0, i2 = 0;
            #pragma unroll
            for (int nf = 0; nf < 4; nf++) {
                #pragma unroll
                for (int j = 0; j < 2; j++) {
                    int cloc = wn * 32 + nf * 8 + 2 * q + j;
                    float sc = fmaf(-2.0f, acc[mf][nf][half * 2 + j], cbs[cloc]);
                    int code = ctbase + cloc;
                    if (sc < v1) { v2 = v1; i2 = i1; v1 = sc; i1 = code; }
                    else if (sc < v2) { v2 = sc; i2 = code; }
                }
            }
            #pragma unroll
            for (int o = 1; o <= 2; o <<= 1) {
                float w1 = __shfl_xor_sync(0xffffffffu, v1, o);
                int   j1 = __shfl_xor_sync(0xffffffffu, i1, o);
                float w2 = __shfl_xor_sync(0xffffffffu, v2, o);
                int   j2 = __shfl_xor_sync(0xffffffffu, i2, o);
                if (w1 < v1 || (w1 == v1 && j1 < i1)) { v2 = v1; i2 = i1; v1 = w1; i1 = j1; }
                else if (w1 < v2 || (w1 == v2 && j1 < i2)) { v2 = w1; i2 = j1; }
                if (w2 < v1 || (w2 == v1 && j2 < i1)) { v2 = v1; i2 = i1; v1 = w2; i1 = j2; }
                else if (w2 < v2 || (w2 == v2 && j2 < i2)) { v2 = w2; i2 = j2; }
            }
            if (q == 0)
                red[rloc * 4 + wn] =
                    make_float4(v1, __int_as_float(i1), v2, __int_as_float(i2));
        }
    }
    __syncthreads();
    if (tid < MT) {
        float v1 = 3.4e38f, v2 = 3.4e38f;
        int i1 = 0x7fffffff, i2 = 0x7fffffff;
        #pragma unroll
        for (int w = 0; w < 4; w++) {
            float4 p = red[tid * 4 + w];
            float w1 = p.x, w2 = p.z;
            int j1 = __float_as_int(p.y), j2 = __float_as_int(p.w);
            if (w1 < v1 || (w1 == v1 && j1 < i1)) { v2 = v1; i2 = i1; v1 = w1; i1 = j1; }
            else if (w1 < v2 || (w1 == v2 && j1 < i2)) { v2 = w1; i2 = j1; }
            if (w2 < v1 || (w2 == v1 && j2 < i1)) { v2 = v1; i2 = i1; v1 = w2; i1 = j2; }
            else if (w2 < v2 || (w2 == v2 && j2 < i2)) { v2 = w2; i2 = j2; }
        }
        g_part[(size_t)(row0 + tid) * NCTQ + blockIdx.y] =
            make_float4(v1, __int_as_float(i1), v2, __int_as_float(i2));
    }
}

// ------------------------------------------------------------- K4: combine + exact rescore + gather
__global__ __launch_bounds__(256) void combine_kernel(const float* __restrict__ Cb,
                                                      float* __restrict__ out_idx_f,
                                                      float4* __restrict__ out_emb4) {
    int row = blockIdx.x * 8 + (threadIdx.x >> 5);
    int lane = threadIdx.x & 31;

    float v1 = 3.4e38f, v2 = 3.4e38f;
    int i1 = 0x7fffffff, i2 = 0x7fffffff;
    if (lane < NCTQ) {
        float4 p = g_part[(size_t)row * NCTQ + lane];
        v1 = p.x; i1 = __float_as_int(p.y);
        v2 = p.z; i2 = __float_as_int(p.w);
    }
    #pragma unroll
    for (int o = 16; o; o >>= 1) {
        float w1 = __shfl_xor_sync(0xffffffffu, v1, o);
        int   j1 = __shfl_xor_sync(0xffffffffu, i1, o);
        float w2 = __shfl_xor_sync(0xffffffffu, v2, o);
        int   j2 = __shfl_xor_sync(0xffffffffu, i2, o);
        if (w1 < v1 || (w1 == v1 && j1 < i1)) { v2 = v1; i2 = i1; v1 = w1; i1 = j1; }
        else if (w1 < v2 || (w1 == v2 && j1 < i2)) { v2 = w1; i2 = j1; }
        if (w2 < v1 || (w2 == v1 && j2 < i1)) { v2 = v1; i2 = i1; v1 = w2; i1 = j2; }
        else if (w2 < v2 || (w2 == v2 && j2 < i2)) { v2 = w2; i2 = j2; }
    }
    // exact fp32 rescore of the two leading candidates
    float d1 = 0.f, d2 = 0.f;
    const float* mrow = &g_means[(size_t)row * DD];
    const float* c1 = &Cb[(size_t)i1 * DD];
    const float* c2 = &Cb[(size_t)i2 * DD];
    for (int d = lane; d < DD; d += 32) {
        float m = mrow[d];
        d1 = fmaf(m, c1[d], d1);
        d2 = fmaf(m, c2[d], d2);
    }
    #pragma unroll
    for (int o = 16; o; o >>= 1) {
        d1 += __shfl_xor_sync(0xffffffffu, d1, o);
        d2 += __shfl_xor_sync(0xffffffffu, d2, o);
    }
    float s1 = fmaf(-2.f, d1, g_cbsq[i1]);
    float s2 = fmaf(-2.f, d2, g_cbsq[i2]);
    int best = (s2 < s1 || (s2 == s1 && i2 < i1)) ? i2 : i1;
    if (lane == 0) {
        g_idx[row] = best;
        out_idx_f[row] = (float)best;
    }
    // fused gather: write winner's embedding (rows hot in L2 from rescore)
    const float4* src = (const float4*)&Cb[(size_t)best * DD];
    float4* dst = out_emb4 + (size_t)row * (DD / 4);
    #pragma unroll
    for (int j = 0; j < 4; j++)
        dst[lane + 32 * j] = src[lane + 32 * j];
}

// ------------------------------------------------------------- K5: loss
__global__ void loss_kernel(float* __restrict__ out_loss) {
    __shared__ float red[1024];
    float s = 0.f;
    for (int n = threadIdx.x; n < NROWS; n += 1024) s += g_s[g_idx[n]];
    red[threadIdx.x] = s;
    __syncthreads();
    for (int st = 512; st > 0; st >>= 1) {
        if (threadIdx.x < st) red[threadIdx.x] += red[threadIdx.x + st];
        __syncthreads();
    }
    if (threadIdx.x == 0)
        out_loss[0] = red[0] / (float)((long long)NROWS * DD);
}

// -------------------------------------------------------------
extern "C" void kernel_launch(void* const* d_in, const int* in_sizes, int n_in,
                              void* d_out, int out_size) {
    const float* E    = (const float*)d_in[1];
    const float* Cb   = (const float*)d_in[2];
    const float* W    = (const float*)d_in[3];
    const float* bias = (const float*)d_in[4];

    float* out      = (float*)d_out;
    float* out_idx  = out;
    float* out_emb  = out + NROWS;
    float* out_loss = out + NROWS + NROWS * DD;

    cudaFuncSetAttribute(gemm_argmin, cudaFuncAttributeMaxDynamicSharedMemorySize, SMEM_GEMM);

    means_kernel<<<(NROWS * (DD / 4) + 255) / 256, 256>>>((const float4*)E);
    cbsplit_kernel<<<(KK * DD / 4 + 255) / 256, 256>>>((const float4*)Cb);
    prep_kernel<<<KK / 8, 256>>>(Cb, W, bias);
    gemm_argmin<<<dim3(NROWS / MT, NCTQ), 512, SMEM_GEMM>>>();
    combine_kernel<<<NROWS / 8, 256>>>(Cb, out_idx, (float4*)out_emb);
    loss_kernel<<<1, 1024>>>(out_loss);
}